// round 5
// baseline (speedup 1.0000x reference)
#include <cuda_runtime.h>
#include <cstdint>

// ---------------------------------------------------------------------------
// SpikingAttention: adaptive-LIF (LSNN) scans + WTA pseudo-softmax
// B=32, T=1000, D=512, U=512
// Blocks 0..31: per-batch merged scan (k/q/v lsnn + wta + att, smem handoffs).
// Blocks 32..3031: GEMM tiles producing feedforward currents chunk-by-chunk.
// Only cross-block sync: per-4-timestep chunk counters (red.release/ld.acquire).
// ---------------------------------------------------------------------------

#define ALPHA 0.9f
#define RHO   0.995f
#define BETA  1.6f

#define NB 32
#define NT 1000
#define NU 512
#define MTOT (NB*NT)          // 32000

#define OUT1_OFF 0ull
#define OUT2_OFF 16384000ull
#define OUT3_OFF 114688000ull
#define OUT4_OFF 180224000ull

// Scratch
__device__ float g_I[3ll * MTOT * NU];   // currents, layout [pop][t*32+b][u]
__device__ int   g_chunk[250];           // per-4t-chunk GEMM completion (target 12)

// ---------------------------------------------------------------------------
__device__ __forceinline__ int ld_acquire(const int* p) {
    int v;
    asm volatile("ld.acquire.gpu.global.s32 %0, [%1];" : "=r"(v) : "l"(p) : "memory");
    return v;
}
__device__ __forceinline__ void red_release_add(int* p, int v) {
    asm volatile("red.release.gpu.global.add.s32 [%0], %1;" :: "l"(p), "r"(v) : "memory");
}
__device__ __forceinline__ void spin_ge(const int* p, int want) {
    while (ld_acquire(p) < want) { __nanosleep(60); }
}

#define FMA_F32X2(acc, a, b) \
    asm("fma.rn.f32x2 %0, %1, %2, %0;" : "+l"(acc) : "l"(a), "l"(b))
#define PACK_DUP2(out, f) \
    asm("mov.b64 %0, {%1, %1};" : "=l"(out) : "f"(f))

#define CP_ASYNC16(smem_addr, gptr) \
    asm volatile("cp.async.cg.shared.global [%0], [%1], 16;" :: "r"(smem_addr), "l"(gptr))
#define CP_COMMIT()  asm volatile("cp.async.commit_group;")
#define CP_WAIT(N)   asm volatile("cp.async.wait_group %0;" :: "n"(N))

__device__ __forceinline__ unsigned smem_u32(const void* p) {
    return (unsigned)__cvta_generic_to_shared(p);
}

// ---------------------------------------------------------------------------
// shared memory (union across roles)
// ---------------------------------------------------------------------------
struct GemmSmem {
    float As[2][128][20];
    float Bs[2][16][128];
};
struct ScanSmem {
    float Ibuf[4][3][512];           // 4 timesteps x (k,q,v) currents  24KB
    unsigned mask[3][16];            // fresh k,q,v spike masks
    unsigned maskZ[16];              // fresh zA mask
    unsigned maskR[16];              // att own spikes (prev step)
    float red[16];
    int totK, totQ, totV, totKQ, totAtt;
    unsigned short listK[528], listQ[528], listV[528];
    unsigned short listKQ[1056];
    unsigned short listAtt[1584];
};

// ---------------------------------------------------------------------------
// List builder: warp-collective (one warp). Lane l contributes word l.
// Ascending indices; returns total.
// ---------------------------------------------------------------------------
__device__ __forceinline__ int build_list(unsigned m, int bias,
                                          unsigned short* list, int list_off)
{
    const int lane = threadIdx.x & 31;
    int c = __popc(m);
    int inc = c;
#pragma unroll
    for (int o = 1; o < 32; o <<= 1) {
        int v = __shfl_up_sync(0xffffffffu, inc, o);
        if (lane >= o) inc += v;
    }
    int off  = list_off + inc - c;
    int base = bias + lane * 32;
    while (m) {
        int j = __ffs((int)m) - 1;
        list[off++] = (unsigned short)(base + j);
        m &= (m - 1);
    }
    return __shfl_sync(0xffffffffu, inc, 31);
}

// 16-wide batched gather (list padded with >=16 zeros past n).
__device__ __forceinline__ float gather16(const float* __restrict__ W,
                                          const unsigned short* list, int n,
                                          int u, float acc)
{
    for (int i = 0; i < n; i += 16) {
        float w[16];
#pragma unroll
        for (int k = 0; k < 16; k++) {
            int j = list[i + k];
            w[k] = W[(size_t)j * 512 + u];
        }
#pragma unroll
        for (int k = 0; k < 16; k++)
            if (i + k < n) acc += w[k];
    }
    return acc;
}

// two-matrix variant: idx<1024 -> Win, else Wrec (idx-1024)
__device__ __forceinline__ float gather16_2(const float* __restrict__ Win,
                                            const float* __restrict__ Wrec,
                                            const unsigned short* list, int n,
                                            int u, float acc)
{
    for (int i = 0; i < n; i += 16) {
        float w[16];
#pragma unroll
        for (int k = 0; k < 16; k++) {
            int j = list[i + k];
            const float* base = (j < 1024) ? (Win + (size_t)j * 512)
                                           : (Wrec + (size_t)(j - 1024) * 512);
            w[k] = base[u];
        }
#pragma unroll
        for (int k = 0; k < 16; k++)
            if (i + k < n) acc += w[k];
    }
    return acc;
}

// ---------------------------------------------------------------------------
// GEMM role: one block = 4 timesteps x 32 batches x 128 cols, K=512.
// ---------------------------------------------------------------------------
__device__ void gemm_role(int g, const float* __restrict__ A,
                          const float* __restrict__ Wk,
                          const float* __restrict__ Wq,
                          const float* __restrict__ Wv,
                          GemmSmem* gs)
{
    const int mchunk = g / 12;
    const int rem    = g % 12;
    const int pop    = rem >> 2;
    const int nt     = rem & 3;
    const float* __restrict__ W = (pop == 0) ? Wk : (pop == 1) ? Wq : Wv;
    float* __restrict__ C = g_I + (size_t)pop * MTOT * NU;

    const int tid = threadIdx.x;
    const int r0 = mchunk * 128;
    const int n0 = nt * 128;
    const int tx = tid & 15;
    const int ty = tid >> 4;

    const int arow = tid >> 2;
    const int aseg = tid & 3;
    const int rg   = r0 + arow;
    const int m    = (rg & 31) * 1000 + (rg >> 5);
    const float* Asrc = A + (size_t)m * 512 + aseg * 4;
    const int brb = tid >> 5;
    const int bcb = tid & 31;
    const float* Bsrc = W + (size_t)brb * 512 + n0 + bcb * 4;

    unsigned adstA[2], adstB[2];
#pragma unroll
    for (int s = 0; s < 2; s++) {
        adstA[s] = smem_u32(&gs->As[s][arow][aseg * 4]);
        adstB[s] = smem_u32(&gs->Bs[s][brb][bcb * 4]);
    }

    unsigned long long acc[4][4];
#pragma unroll
    for (int i = 0; i < 4; i++)
#pragma unroll
        for (int j = 0; j < 4; j++) acc[i][j] = 0ull;

    CP_ASYNC16(adstA[0], Asrc);
    CP_ASYNC16(adstB[0], Bsrc);
    CP_COMMIT();

    for (int kt = 0; kt < 32; kt++) {
        if (kt < 31) {
            const int k0 = (kt + 1) * 16;
            const int s = (kt + 1) & 1;
            CP_ASYNC16(adstA[s], Asrc + k0);
            CP_ASYNC16(adstB[s], Bsrc + (size_t)k0 * 512);
            CP_COMMIT();
            CP_WAIT(1);
        } else {
            CP_WAIT(0);
        }
        __syncthreads();

        const int s = kt & 1;
#pragma unroll
        for (int kk = 0; kk < 16; kk++) {
            float a0 = gs->As[s][ty * 4 + 0][kk];
            float a1 = gs->As[s][ty * 4 + 1][kk];
            float a2 = gs->As[s][ty * 4 + 2][kk];
            float a3 = gs->As[s][ty * 4 + 3][kk];
            ulonglong2 b01 = *(const ulonglong2*)&gs->Bs[s][kk][tx * 8];
            ulonglong2 b23 = *(const ulonglong2*)&gs->Bs[s][kk][tx * 8 + 4];
            unsigned long long bp0 = b01.x, bp1 = b01.y, bp2 = b23.x, bp3 = b23.y;
            unsigned long long ad;
            PACK_DUP2(ad, a0);
            FMA_F32X2(acc[0][0], ad, bp0); FMA_F32X2(acc[0][1], ad, bp1);
            FMA_F32X2(acc[0][2], ad, bp2); FMA_F32X2(acc[0][3], ad, bp3);
            PACK_DUP2(ad, a1);
            FMA_F32X2(acc[1][0], ad, bp0); FMA_F32X2(acc[1][1], ad, bp1);
            FMA_F32X2(acc[1][2], ad, bp2); FMA_F32X2(acc[1][3], ad, bp3);
            PACK_DUP2(ad, a2);
            FMA_F32X2(acc[2][0], ad, bp0); FMA_F32X2(acc[2][1], ad, bp1);
            FMA_F32X2(acc[2][2], ad, bp2); FMA_F32X2(acc[2][3], ad, bp3);
            PACK_DUP2(ad, a3);
            FMA_F32X2(acc[3][0], ad, bp0); FMA_F32X2(acc[3][1], ad, bp1);
            FMA_F32X2(acc[3][2], ad, bp2); FMA_F32X2(acc[3][3], ad, bp3);
        }
        __syncthreads();
    }

#pragma unroll
    for (int i = 0; i < 4; i++) {
        float* Crow = C + (size_t)(r0 + ty * 4 + i) * 512 + n0 + tx * 8;
        ulonglong2 v0; v0.x = acc[i][0]; v0.y = acc[i][1];
        ulonglong2 v1; v1.x = acc[i][2]; v1.y = acc[i][3];
        *(ulonglong2*)Crow = v0;
        *((ulonglong2*)Crow + 1) = v1;
    }
    __syncthreads();
    if (tid == 0) red_release_add(&g_chunk[mchunk], 1);
}

// ---------------------------------------------------------------------------
// Merged per-batch scan role: k/q/v lsnn + wta + att, all in one block.
// ---------------------------------------------------------------------------
__device__ void batch_role(int b,
                           const float* __restrict__ WkR,
                           const float* __restrict__ WqR,
                           const float* __restrict__ WvR,
                           const float* __restrict__ Wa,
                           const float* __restrict__ Wb,
                           const float* __restrict__ Win,
                           const float* __restrict__ Wrec,
                           float* __restrict__ d_out, ScanSmem* ss)
{
    float* __restrict__ out1 = d_out + OUT1_OFF;
    float* __restrict__ out2 = d_out + OUT2_OFF;
    float* __restrict__ out3 = d_out + OUT3_OFF;
    float* __restrict__ out4 = d_out + OUT4_OFF;

    const int tid = threadIdx.x, u = tid, warp = tid >> 5, lane = tid & 31;

    if (tid < 16) {
        ss->mask[0][tid] = 0u; ss->mask[1][tid] = 0u; ss->mask[2][tid] = 0u;
        ss->maskR[tid] = 0u;
    }
    __syncthreads();

    float vK = 0.f, aK = 0.f, zK = 0.f;
    float vQ = 0.f, aQ = 0.f, zQ = 0.f;
    float vV = 0.f, aV = 0.f, zV = 0.f;
    float vA = 0.f, vB = 0.f, zA = 0.f, zB = 0.f;
    float vT = 0.f, aT = 0.f, zT = 0.f;

    for (int t = 0; t < NT; t++) {
        const int s = t & 3;
        if (s == 0) {
            const int c = t >> 2;
            if (tid == 0) spin_ge(&g_chunk[c], 12);
            __syncthreads();
            // bulk-load 4 steps x 3 pops of currents (3 x 16B per thread)
#pragma unroll
            for (int l = 0; l < 3; l++) {
                int idx = l * 512 + tid;          // 0..1535
                int sp  = idx >> 7;               // 0..11
                int p_  = sp % 3;
                int st_ = sp / 3;                 // 0..3
                int u4  = (idx & 127) * 4;
                const float* src = g_I + ((size_t)p_ * MTOT + (size_t)(t + st_) * 32 + b) * 512 + u4;
                CP_ASYNC16(smem_u32(&ss->Ibuf[st_][p_][u4]), src);
            }
            CP_COMMIT(); CP_WAIT(0);
            __syncthreads();
        }

        // ---- Phase 1: lists from prev-step masks (3 warps in parallel)
        if (warp == 0) {
            int tot = build_list(lane < 16 ? ss->mask[0][lane] : 0u, 0, ss->listK, 0);
            if (lane < 16) ss->listK[tot + lane] = 0;
            if (lane == 0) ss->totK = tot;
        } else if (warp == 1) {
            int tot = build_list(lane < 16 ? ss->mask[1][lane] : 0u, 0, ss->listQ, 0);
            if (lane < 16) ss->listQ[tot + lane] = 0;
            if (lane == 0) ss->totQ = tot;
        } else if (warp == 2) {
            int tot = build_list(lane < 16 ? ss->mask[2][lane] : 0u, 0, ss->listV, 0);
            if (lane < 16) ss->listV[tot + lane] = 0;
            if (lane == 0) ss->totV = tot;
        }
        __syncthreads();                                    // B1

        // ---- Phase 2: k,q,v gathers (interleaved for MLP) + lsnn math
        const int nK = ss->totK, nQ = ss->totQ, nV = ss->totV;
        float accK = ss->Ibuf[s][0][u];
        float accQ = ss->Ibuf[s][1][u];
        float accV = ss->Ibuf[s][2][u];
        {
            int nmax = nK > nQ ? nK : nQ;
            if (nV > nmax) nmax = nV;
            for (int i = 0; i < nmax; i += 8) {
                float wk[8], wq[8], wv[8];
                const bool dk = i < nK, dq = i < nQ, dv = i < nV;
#pragma unroll
                for (int k2 = 0; k2 < 8; k2++) {
                    if (dk) wk[k2] = WkR[(size_t)ss->listK[i + k2] * 512 + u];
                    if (dq) wq[k2] = WqR[(size_t)ss->listQ[i + k2] * 512 + u];
                    if (dv) wv[k2] = WvR[(size_t)ss->listV[i + k2] * 512 + u];
                }
#pragma unroll
                for (int k2 = 0; k2 < 8; k2++) {
                    if (i + k2 < nK) accK += wk[k2];
                    if (i + k2 < nQ) accQ += wq[k2];
                    if (i + k2 < nV) accV += wv[k2];
                }
            }
        }

        float aKn = RHO * aK + zK, thrK = 1.0f + BETA * aKn;
        float vKn = ALPHA * vK + accK - zK * thrK, vscK = vKn - thrK;
        float zKn = (vscK > 0.f) ? 1.f : 0.f;
        float aQn = RHO * aQ + zQ, thrQ = 1.0f + BETA * aQn;
        float vQn = ALPHA * vQ + accQ - zQ * thrQ, vscQ = vQn - thrQ;
        float zQn = (vscQ > 0.f) ? 1.f : 0.f;
        float aVn = RHO * aV + zV, thrV = 1.0f + BETA * aVn;
        float vVn = ALPHA * vV + accV - zV * thrV, vscV = vVn - thrV;
        float zVn = (vscV > 0.f) ? 1.f : 0.f;

        unsigned balK = __ballot_sync(0xffffffffu, zKn > 0.f);
        unsigned balQ = __ballot_sync(0xffffffffu, zQn > 0.f);
        unsigned balV = __ballot_sync(0xffffffffu, zVn > 0.f);
        if (lane == 0) {
            ss->mask[0][warp] = balK;
            ss->mask[1][warp] = balQ;
            ss->mask[2][warp] = balV;
        }

        const size_t base = (size_t)b * NT + t;
        __stcs(&out2[base * 3072 + 0 * 512 + u], zKn);
        __stcs(&out2[base * 3072 + 1 * 512 + u], zQn);
        __stcs(&out2[base * 3072 + 2 * 512 + u], zVn);
        __stcs(&out3[base * 2048 + 0 * 512 + u], thrK);
        __stcs(&out3[base * 2048 + 1 * 512 + u], thrQ);
        __stcs(&out3[base * 2048 + 2 * 512 + u], thrV);
        __stcs(&out4[base * 3072 + 0 * 512 + u], vscK);
        __stcs(&out4[base * 3072 + 1 * 512 + u], vscQ);
        __stcs(&out4[base * 3072 + 2 * 512 + u], vscV);
        __syncthreads();                                    // B2

        // ---- Phase 3: WTA pop A
        if (warp == 0) {
            unsigned m = (lane < 16) ? ss->mask[0][lane] : ss->mask[1][lane - 16];
            int tot = build_list(m, 0, ss->listKQ, 0);      // K:0..511, Q:512..1023
            if (lane < 16) ss->listKQ[tot + lane] = 0;
            if (lane == 0) ss->totKQ = tot;
        }
        __syncthreads();                                    // B3
        const int nKQ = ss->totKQ;

        float accA = gather16(Wa, ss->listKQ, nKQ, u, 0.f);
        float vAn = ALPHA * vA + accA - zA;
        float vscA = vAn - 1.0f;

        float mx = vAn;
#pragma unroll
        for (int o = 16; o > 0; o >>= 1) mx = fmaxf(mx, __shfl_xor_sync(0xffffffffu, mx, o));
        if (lane == 0) ss->red[warp] = mx;
        __syncthreads();                                    // B4
        float mm = ss->red[lane & 15];
#pragma unroll
        for (int o = 8; o > 0; o >>= 1) mm = fmaxf(mm, __shfl_xor_sync(0xffffffffu, mm, o));

        float winner = (vAn == mm) ? 1.f : 0.f;
        float zAn = (vscA > 0.f) ? winner : 0.f;
        unsigned balZ = __ballot_sync(0xffffffffu, zAn > 0.f);
        if (lane == 0) ss->maskZ[warp] = balZ;
        __syncthreads();                                    // B5

        // ---- Phase 4: WTA pop B + att
        float accB = 0.f;
#pragma unroll
        for (int w = 0; w < 16; w++) {
            unsigned mb = ss->maskZ[w];
            while (mb) {
                int j = __ffs((int)mb) - 1;
                accB += Wb[(size_t)(w * 32 + j) * 512 + u];
                mb &= mb - 1;
            }
        }
        float vBn = ALPHA * vB + accB - zB;
        float vscB = vBn - 1.0f;
        float zBn = (vscB > 0.f) ? 1.f : 0.f;

        __stcs(&out2[base * 3072 + 3 * 512 + u], zAn);
        __stcs(&out2[base * 3072 + 4 * 512 + u], zBn);
        __stcs(&out4[base * 3072 + 3 * 512 + u], vscA);
        __stcs(&out4[base * 3072 + 4 * 512 + u], vscB);

        if (warp == 0) {
            unsigned m1 = (lane < 16) ? ss->mask[2][lane] : ss->maskZ[lane - 16];
            int t1 = build_list(m1, 0, ss->listAtt, 0);     // V:0..511, zA:512..1023
            unsigned m2 = (lane < 16) ? ss->maskR[lane] : 0u;
            int t2 = build_list(m2, 1024, ss->listAtt, t1); // rec: 1024..1535
            int tot = t1 + t2;
            if (lane < 16) ss->listAtt[tot + lane] = 0;
            if (lane == 0) ss->totAtt = tot;
        }
        __syncthreads();                                    // B6
        const int nAtt = ss->totAtt;

        float accT = gather16_2(Win, Wrec, ss->listAtt, nAtt, u, 0.f);
        float aTn = RHO * aT + zT, thrT = 1.0f + BETA * aTn;
        float vTn = ALPHA * vT + accT - zT * thrT, vscT = vTn - thrT;
        float zTn = (vscT > 0.f) ? 1.f : 0.f;

        unsigned balR = __ballot_sync(0xffffffffu, zTn > 0.f);
        if (lane == 0) ss->maskR[warp] = balR;

        __stcs(&out1[base * 512 + u], zTn);
        __stcs(&out2[base * 3072 + 5 * 512 + u], zTn);
        __stcs(&out3[base * 2048 + 3 * 512 + u], thrT);
        __stcs(&out4[base * 3072 + 5 * 512 + u], vscT);

        vK = vKn; aK = aKn; zK = zKn;
        vQ = vQn; aQ = aQn; zQ = zQn;
        vV = vVn; aV = aVn; zV = zVn;
        vA = vAn; vB = vBn; zA = zAn; zB = zBn;
        vT = vTn; aT = aTn; zT = zTn;
        __syncthreads();                                    // B7 (end of step)
    }
}

// ---------------------------------------------------------------------------
__global__ void reset_kernel()
{
    if (threadIdx.x < 250) g_chunk[threadIdx.x] = 0;
}

__global__ __launch_bounds__(512, 2) void fused_kernel(
    const float* __restrict__ x,
    const float* __restrict__ Wk_in, const float* __restrict__ Wk_rec,
    const float* __restrict__ Wq_in, const float* __restrict__ Wq_rec,
    const float* __restrict__ Wv_in, const float* __restrict__ Wv_rec,
    const float* __restrict__ Watt_in, const float* __restrict__ Watt_rec,
    const float* __restrict__ Wwta_a, const float* __restrict__ Wwta_b,
    float* __restrict__ d_out)
{
    __shared__ __align__(16) unsigned char smem_raw[
        sizeof(GemmSmem) > sizeof(ScanSmem) ? sizeof(GemmSmem) : sizeof(ScanSmem)];
    const int bid = blockIdx.x;

    if (bid >= 32) {
        gemm_role(bid - 32, x, Wk_in, Wq_in, Wv_in, (GemmSmem*)smem_raw);
        return;
    }
    batch_role(bid, Wk_rec, Wq_rec, Wv_rec, Wwta_a, Wwta_b,
               Watt_in, Watt_rec, d_out, (ScanSmem*)smem_raw);
}

// ---------------------------------------------------------------------------
extern "C" void kernel_launch(void* const* d_in, const int* in_sizes, int n_in,
                              void* d_out, int out_size)
{
    const float* x        = (const float*)d_in[0];
    const float* Wk_in    = (const float*)d_in[1];
    const float* Wk_rec   = (const float*)d_in[2];
    const float* Wq_in    = (const float*)d_in[3];
    const float* Wq_rec   = (const float*)d_in[4];
    const float* Wv_in    = (const float*)d_in[5];
    const float* Wv_rec   = (const float*)d_in[6];
    const float* Watt_in  = (const float*)d_in[7];
    const float* Watt_rec = (const float*)d_in[8];
    const float* Wwta_a   = (const float*)d_in[9];
    const float* Wwta_b   = (const float*)d_in[10];
    float* out = (float*)d_out;

    (void)in_sizes; (void)n_in; (void)out_size;

    reset_kernel<<<1, 256>>>();
    fused_kernel<<<32 + 3000, 512>>>(x, Wk_in, Wk_rec, Wq_in, Wq_rec,
                                     Wv_in, Wv_rec, Watt_in, Watt_rec,
                                     Wwta_a, Wwta_b, out);
}

// round 6
// speedup vs baseline: 1.5281x; 1.5281x over previous
#include <cuda_runtime.h>
#include <cstdint>

// ---------------------------------------------------------------------------
// SpikingAttention: adaptive-LIF (LSNN) scans + WTA pseudo-softmax
// B=32, T=1000, D=512, U=512
// Blocks 0..31  : kqv role (k,q,v lsnn interleaved, one block per batch)
// Blocks 32..63 : wta role
// Blocks 64..95 : att role
// Blocks 96..3095: GEMM tiles (feedforward currents, 4-timestep chunks)
// 96 scan blocks (<148) => placement leaves >=1 GEMM block resident per SM.
// ---------------------------------------------------------------------------

#define ALPHA 0.9f
#define RHO   0.995f
#define BETA  1.6f

#define NB 32
#define NT 1000
#define NU 512
#define MTOT (NB*NT)

#define OUT1_OFF 0ull
#define OUT2_OFF 16384000ull
#define OUT3_OFF 114688000ull
#define OUT4_OFF 180224000ull

__device__ float    g_I[3ll * MTOT * NU];        // [pop][t*32+b][u]
__device__ unsigned g_spk[3ll * MTOT * 16];      // [pop][b][t][16]
__device__ unsigned g_zA[(long long)MTOT * 16];  // [b][t][16]
__device__ int      g_flag[64];                  // [0..31] kqv step, [32..63] zA step
__device__ int      g_chunk[250];                // GEMM chunk completion (target 12)

// ---------------------------------------------------------------------------
__device__ __forceinline__ int ld_acquire(const int* p) {
    int v;
    asm volatile("ld.acquire.gpu.global.s32 %0, [%1];" : "=r"(v) : "l"(p) : "memory");
    return v;
}
__device__ __forceinline__ void st_release(int* p, int v) {
    asm volatile("st.release.gpu.global.s32 [%0], %1;" :: "l"(p), "r"(v) : "memory");
}
__device__ __forceinline__ void red_release_add(int* p, int v) {
    asm volatile("red.release.gpu.global.add.s32 [%0], %1;" :: "l"(p), "r"(v) : "memory");
}
__device__ __forceinline__ void spin_ge(const int* p, int want) {
    while (ld_acquire(p) < want) { __nanosleep(60); }
}

#define FMA_F32X2(acc, a, b) \
    asm("fma.rn.f32x2 %0, %1, %2, %0;" : "+l"(acc) : "l"(a), "l"(b))
#define PACK_DUP2(out, f) \
    asm("mov.b64 %0, {%1, %1};" : "=l"(out) : "f"(f))

#define CP_ASYNC16(smem_addr, gptr) \
    asm volatile("cp.async.cg.shared.global [%0], [%1], 16;" :: "r"(smem_addr), "l"(gptr))
#define CP_COMMIT()  asm volatile("cp.async.commit_group;")
#define CP_WAIT(N)   asm volatile("cp.async.wait_group %0;" :: "n"(N))

__device__ __forceinline__ unsigned smem_u32(const void* p) {
    return (unsigned)__cvta_generic_to_shared(p);
}

// ---------------------------------------------------------------------------
struct GemmSmem {
    float As[2][128][20];
    float Bs[2][16][128];
};
struct ScanSmem {
    float Ibuf[4][3][512];             // kqv only: 4 steps x 3 pops
    unsigned mask[3][16];
    unsigned maskZ[16];
    unsigned maskR[16];
    float red[16];
    int totK, totQ, totV, totKQ, totAtt;
    unsigned short listK[528], listQ[528], listV[528];
    unsigned short listKQ[1056];
    unsigned short listAtt[1584];
};

// ---------------------------------------------------------------------------
__device__ __forceinline__ int build_list(unsigned m, int bias,
                                          unsigned short* list, int list_off)
{
    const int lane = threadIdx.x & 31;
    int c = __popc(m);
    int inc = c;
#pragma unroll
    for (int o = 1; o < 32; o <<= 1) {
        int v = __shfl_up_sync(0xffffffffu, inc, o);
        if (lane >= o) inc += v;
    }
    int off  = list_off + inc - c;
    int base = bias + lane * 32;
    while (m) {
        int j = __ffs((int)m) - 1;
        list[off++] = (unsigned short)(base + j);
        m &= (m - 1);
    }
    return __shfl_sync(0xffffffffu, inc, 31);
}

__device__ __forceinline__ float gather16(const float* __restrict__ W,
                                          const unsigned short* list, int n,
                                          int u, float acc)
{
    for (int i = 0; i < n; i += 16) {
        float w[16];
#pragma unroll
        for (int k = 0; k < 16; k++) {
            int j = list[i + k];
            w[k] = W[(size_t)j * 512 + u];
        }
#pragma unroll
        for (int k = 0; k < 16; k++)
            if (i + k < n) acc += w[k];
    }
    return acc;
}

__device__ __forceinline__ float gather16_2(const float* __restrict__ Win,
                                            const float* __restrict__ Wrec,
                                            const unsigned short* list, int n,
                                            int u, float acc)
{
    for (int i = 0; i < n; i += 16) {
        float w[16];
#pragma unroll
        for (int k = 0; k < 16; k++) {
            int j = list[i + k];
            const float* base = (j < 1024) ? (Win + (size_t)j * 512)
                                           : (Wrec + (size_t)(j - 1024) * 512);
            w[k] = base[u];
        }
#pragma unroll
        for (int k = 0; k < 16; k++)
            if (i + k < n) acc += w[k];
    }
    return acc;
}

// ---------------------------------------------------------------------------
// GEMM role (proven): one block = 4 timesteps x 32 batches x 128 cols, K=512.
// ---------------------------------------------------------------------------
__device__ void gemm_role(int g, const float* __restrict__ A,
                          const float* __restrict__ Wk,
                          const float* __restrict__ Wq,
                          const float* __restrict__ Wv,
                          GemmSmem* gs)
{
    const int mchunk = g / 12;
    const int rem    = g % 12;
    const int pop    = rem >> 2;
    const int nt     = rem & 3;
    const float* __restrict__ W = (pop == 0) ? Wk : (pop == 1) ? Wq : Wv;
    float* __restrict__ C = g_I + (size_t)pop * MTOT * NU;

    const int tid = threadIdx.x;
    const int r0 = mchunk * 128;
    const int n0 = nt * 128;
    const int tx = tid & 15;
    const int ty = tid >> 4;

    const int arow = tid >> 2;
    const int aseg = tid & 3;
    const int rg   = r0 + arow;
    const int m    = (rg & 31) * 1000 + (rg >> 5);
    const float* Asrc = A + (size_t)m * 512 + aseg * 4;
    const int brb = tid >> 5;
    const int bcb = tid & 31;
    const float* Bsrc = W + (size_t)brb * 512 + n0 + bcb * 4;

    unsigned adstA[2], adstB[2];
#pragma unroll
    for (int s = 0; s < 2; s++) {
        adstA[s] = smem_u32(&gs->As[s][arow][aseg * 4]);
        adstB[s] = smem_u32(&gs->Bs[s][brb][bcb * 4]);
    }

    unsigned long long acc[4][4];
#pragma unroll
    for (int i = 0; i < 4; i++)
#pragma unroll
        for (int j = 0; j < 4; j++) acc[i][j] = 0ull;

    CP_ASYNC16(adstA[0], Asrc);
    CP_ASYNC16(adstB[0], Bsrc);
    CP_COMMIT();

    for (int kt = 0; kt < 32; kt++) {
        if (kt < 31) {
            const int k0 = (kt + 1) * 16;
            const int s = (kt + 1) & 1;
            CP_ASYNC16(adstA[s], Asrc + k0);
            CP_ASYNC16(adstB[s], Bsrc + (size_t)k0 * 512);
            CP_COMMIT();
            CP_WAIT(1);
        } else {
            CP_WAIT(0);
        }
        __syncthreads();

        const int s = kt & 1;
#pragma unroll
        for (int kk = 0; kk < 16; kk++) {
            float a0 = gs->As[s][ty * 4 + 0][kk];
            float a1 = gs->As[s][ty * 4 + 1][kk];
            float a2 = gs->As[s][ty * 4 + 2][kk];
            float a3 = gs->As[s][ty * 4 + 3][kk];
            ulonglong2 b01 = *(const ulonglong2*)&gs->Bs[s][kk][tx * 8];
            ulonglong2 b23 = *(const ulonglong2*)&gs->Bs[s][kk][tx * 8 + 4];
            unsigned long long bp0 = b01.x, bp1 = b01.y, bp2 = b23.x, bp3 = b23.y;
            unsigned long long ad;
            PACK_DUP2(ad, a0);
            FMA_F32X2(acc[0][0], ad, bp0); FMA_F32X2(acc[0][1], ad, bp1);
            FMA_F32X2(acc[0][2], ad, bp2); FMA_F32X2(acc[0][3], ad, bp3);
            PACK_DUP2(ad, a1);
            FMA_F32X2(acc[1][0], ad, bp0); FMA_F32X2(acc[1][1], ad, bp1);
            FMA_F32X2(acc[1][2], ad, bp2); FMA_F32X2(acc[1][3], ad, bp3);
            PACK_DUP2(ad, a2);
            FMA_F32X2(acc[2][0], ad, bp0); FMA_F32X2(acc[2][1], ad, bp1);
            FMA_F32X2(acc[2][2], ad, bp2); FMA_F32X2(acc[2][3], ad, bp3);
            PACK_DUP2(ad, a3);
            FMA_F32X2(acc[3][0], ad, bp0); FMA_F32X2(acc[3][1], ad, bp1);
            FMA_F32X2(acc[3][2], ad, bp2); FMA_F32X2(acc[3][3], ad, bp3);
        }
        __syncthreads();
    }

#pragma unroll
    for (int i = 0; i < 4; i++) {
        float* Crow = C + (size_t)(r0 + ty * 4 + i) * 512 + n0 + tx * 8;
        ulonglong2 v0; v0.x = acc[i][0]; v0.y = acc[i][1];
        ulonglong2 v1; v1.x = acc[i][2]; v1.y = acc[i][3];
        *(ulonglong2*)Crow = v0;
        *((ulonglong2*)Crow + 1) = v1;
    }
    __syncthreads();
    if (tid == 0) red_release_add(&g_chunk[mchunk], 1);
}

// ---------------------------------------------------------------------------
// kqv role: k,q,v lsnn interleaved for one batch. 2 bars/step.
// ---------------------------------------------------------------------------
__device__ void kqv_role(int b,
                         const float* __restrict__ WkR,
                         const float* __restrict__ WqR,
                         const float* __restrict__ WvR,
                         float* __restrict__ d_out, ScanSmem* ss)
{
    unsigned* __restrict__ spkK = g_spk + ((size_t)0 * NB + b) * NT * 16;
    unsigned* __restrict__ spkQ = g_spk + ((size_t)1 * NB + b) * NT * 16;
    unsigned* __restrict__ spkV = g_spk + ((size_t)2 * NB + b) * NT * 16;

    float* __restrict__ out2 = d_out + OUT2_OFF;
    float* __restrict__ out3 = d_out + OUT3_OFF;
    float* __restrict__ out4 = d_out + OUT4_OFF;

    const int tid = threadIdx.x, u = tid, warp = tid >> 5, lane = tid & 31;

    if (tid < 16) {
        ss->mask[0][tid] = 0u; ss->mask[1][tid] = 0u; ss->mask[2][tid] = 0u;
    }
    __syncthreads();

    float vK = 0.f, aK = 0.f, zK = 0.f;
    float vQ = 0.f, aQ = 0.f, zQ = 0.f;
    float vV = 0.f, aV = 0.f, zV = 0.f;

    for (int t = 0; t < NT; t++) {
        const int s = t & 3;
        if (s == 0) {
            if (tid == 0) spin_ge(&g_chunk[t >> 2], 12);
            __syncthreads();
#pragma unroll
            for (int l = 0; l < 3; l++) {
                int idx = l * 512 + tid;
                int sp  = idx >> 7;
                int p_  = sp % 3;
                int st_ = sp / 3;
                int u4  = (idx & 127) * 4;
                const float* src = g_I + ((size_t)p_ * MTOT + (size_t)(t + st_) * 32 + b) * 512 + u4;
                CP_ASYNC16(smem_u32(&ss->Ibuf[st_][p_][u4]), src);
            }
            CP_COMMIT(); CP_WAIT(0);
            __syncthreads();
        }

        if (warp == 0) {
            int tot = build_list(lane < 16 ? ss->mask[0][lane] : 0u, 0, ss->listK, 0);
            if (lane < 16) ss->listK[tot + lane] = 0;
            if (lane == 0) ss->totK = tot;
        } else if (warp == 1) {
            int tot = build_list(lane < 16 ? ss->mask[1][lane] : 0u, 0, ss->listQ, 0);
            if (lane < 16) ss->listQ[tot + lane] = 0;
            if (lane == 0) ss->totQ = tot;
        } else if (warp == 2) {
            int tot = build_list(lane < 16 ? ss->mask[2][lane] : 0u, 0, ss->listV, 0);
            if (lane < 16) ss->listV[tot + lane] = 0;
            if (lane == 0) ss->totV = tot;
        }
        __syncthreads();                                    // B1

        const int nK = ss->totK, nQ = ss->totQ, nV = ss->totV;
        float accK = ss->Ibuf[s][0][u];
        float accQ = ss->Ibuf[s][1][u];
        float accV = ss->Ibuf[s][2][u];
        {
            int nmax = nK > nQ ? nK : nQ;
            if (nV > nmax) nmax = nV;
            for (int i = 0; i < nmax; i += 8) {
                float wk[8], wq[8], wv[8];
                const bool dk = i < nK, dq = i < nQ, dv = i < nV;
#pragma unroll
                for (int k2 = 0; k2 < 8; k2++) {
                    if (dk) wk[k2] = WkR[(size_t)ss->listK[i + k2] * 512 + u];
                    if (dq) wq[k2] = WqR[(size_t)ss->listQ[i + k2] * 512 + u];
                    if (dv) wv[k2] = WvR[(size_t)ss->listV[i + k2] * 512 + u];
                }
#pragma unroll
                for (int k2 = 0; k2 < 8; k2++) {
                    if (i + k2 < nK) accK += wk[k2];
                    if (i + k2 < nQ) accQ += wq[k2];
                    if (i + k2 < nV) accV += wv[k2];
                }
            }
        }

        float aKn = RHO * aK + zK, thrK = 1.0f + BETA * aKn;
        float vKn = ALPHA * vK + accK - zK * thrK, vscK = vKn - thrK;
        float zKn = (vscK > 0.f) ? 1.f : 0.f;
        float aQn = RHO * aQ + zQ, thrQ = 1.0f + BETA * aQn;
        float vQn = ALPHA * vQ + accQ - zQ * thrQ, vscQ = vQn - thrQ;
        float zQn = (vscQ > 0.f) ? 1.f : 0.f;
        float aVn = RHO * aV + zV, thrV = 1.0f + BETA * aVn;
        float vVn = ALPHA * vV + accV - zV * thrV, vscV = vVn - thrV;
        float zVn = (vscV > 0.f) ? 1.f : 0.f;

        unsigned balK = __ballot_sync(0xffffffffu, zKn > 0.f);
        unsigned balQ = __ballot_sync(0xffffffffu, zQn > 0.f);
        unsigned balV = __ballot_sync(0xffffffffu, zVn > 0.f);
        if (lane == 0) {
            ss->mask[0][warp] = balK;
            ss->mask[1][warp] = balQ;
            ss->mask[2][warp] = balV;
            spkK[(size_t)t * 16 + warp] = balK;
            spkQ[(size_t)t * 16 + warp] = balQ;
            spkV[(size_t)t * 16 + warp] = balV;
        }
        __syncthreads();                                    // B2
        if (tid == 0) st_release(&g_flag[b], t + 1);

        const size_t base = (size_t)b * NT + t;
        __stcs(&out2[base * 3072 + 0 * 512 + u], zKn);
        __stcs(&out2[base * 3072 + 1 * 512 + u], zQn);
        __stcs(&out2[base * 3072 + 2 * 512 + u], zVn);
        __stcs(&out3[base * 2048 + 0 * 512 + u], thrK);
        __stcs(&out3[base * 2048 + 1 * 512 + u], thrQ);
        __stcs(&out3[base * 2048 + 2 * 512 + u], thrV);
        __stcs(&out4[base * 3072 + 0 * 512 + u], vscK);
        __stcs(&out4[base * 3072 + 1 * 512 + u], vscQ);
        __stcs(&out4[base * 3072 + 2 * 512 + u], vscV);

        vK = vKn; aK = aKn; zK = zKn;
        vQ = vQn; aQ = aQn; zQ = zQn;
        vV = vVn; aV = aVn; zV = zVn;
    }
}

// ---------------------------------------------------------------------------
// WTA role. 4 bars/step.
// ---------------------------------------------------------------------------
__device__ void wta_role(int b, const float* __restrict__ Wa,
                         const float* __restrict__ Wb,
                         float* __restrict__ d_out, ScanSmem* ss)
{
    const unsigned* __restrict__ spkK = g_spk + (size_t)b * NT * 16;
    const unsigned* __restrict__ spkQ = g_spk + ((size_t)NB + b) * NT * 16;
    unsigned* __restrict__ zAout      = g_zA + (size_t)b * NT * 16;

    float* __restrict__ out2 = d_out + OUT2_OFF;
    float* __restrict__ out4 = d_out + OUT4_OFF;

    const int tid = threadIdx.x, u = tid, warp = tid >> 5, lane = tid & 31;

    float vA = 0.f, vB = 0.f, zA = 0.f, zB = 0.f;

    for (int t = 0; t < NT; t++) {
        if (warp == 0) {
            if (lane == 0) spin_ge(&g_flag[b], t + 1);
            __syncwarp();
            unsigned m = (lane < 16) ? __ldcg(&spkK[(size_t)t * 16 + lane])
                                     : __ldcg(&spkQ[(size_t)t * 16 + (lane - 16)]);
            int tot = build_list(m, 0, ss->listKQ, 0);
            if (lane < 16) ss->listKQ[tot + lane] = 0;
            if (lane == 0) ss->totKQ = tot;
        }
        __syncthreads();                                   // B1
        const int nsp = ss->totKQ;

        float acc = gather16(Wa, ss->listKQ, nsp, u, 0.f);

        float vAn = ALPHA * vA + acc - zA;
        float vscA = vAn - 1.0f;

        float mx = vAn;
#pragma unroll
        for (int o = 16; o > 0; o >>= 1) mx = fmaxf(mx, __shfl_xor_sync(0xffffffffu, mx, o));
        if (lane == 0) ss->red[warp] = mx;
        __syncthreads();                                   // B2
        float mm = ss->red[lane & 15];
#pragma unroll
        for (int o = 8; o > 0; o >>= 1) mm = fmaxf(mm, __shfl_xor_sync(0xffffffffu, mm, o));

        float winner = (vAn == mm) ? 1.f : 0.f;
        float zAn = (vscA > 0.f) ? winner : 0.f;

        unsigned balZ = __ballot_sync(0xffffffffu, zAn > 0.f);
        if (lane == 0) {
            ss->maskZ[warp] = balZ;
            zAout[(size_t)t * 16 + warp] = balZ;
        }
        __syncthreads();                                   // B3
        if (tid == 0) st_release(&g_flag[32 + b], t + 1);

        float accB = 0.f;
#pragma unroll
        for (int w = 0; w < 16; w++) {
            unsigned mb = ss->maskZ[w];
            while (mb) {
                int j = __ffs((int)mb) - 1;
                accB += Wb[(size_t)(w * 32 + j) * 512 + u];
                mb &= mb - 1;
            }
        }
        float vBn = ALPHA * vB + accB - zB;
        float vscB = vBn - 1.0f;
        float zBn = (vscB > 0.f) ? 1.f : 0.f;

        const size_t base = (size_t)b * NT + t;
        __stcs(&out2[base * 3072 + 3 * 512 + u], zAn);
        __stcs(&out2[base * 3072 + 4 * 512 + u], zBn);
        __stcs(&out4[base * 3072 + 3 * 512 + u], vscA);
        __stcs(&out4[base * 3072 + 4 * 512 + u], vscB);

        vA = vAn; vB = vBn; zA = zAn; zB = zBn;
        __syncthreads();                                   // B4
    }
}

// ---------------------------------------------------------------------------
// Attention LSNN role. 2 bars/step.
// ---------------------------------------------------------------------------
__device__ void att_role(int b, const float* __restrict__ Win,
                         const float* __restrict__ Wrec,
                         float* __restrict__ d_out, ScanSmem* ss)
{
    const unsigned* __restrict__ spkV = g_spk + ((size_t)2 * NB + b) * NT * 16;
    const unsigned* __restrict__ zAin = g_zA + (size_t)b * NT * 16;

    float* __restrict__ out1 = d_out + OUT1_OFF;
    float* __restrict__ out2 = d_out + OUT2_OFF;
    float* __restrict__ out3 = d_out + OUT3_OFF;
    float* __restrict__ out4 = d_out + OUT4_OFF;

    const int tid = threadIdx.x, u = tid, warp = tid >> 5, lane = tid & 31;

    if (tid < 16) ss->maskR[tid] = 0u;
    __syncthreads();

    float v = 0.f, a = 0.f, z = 0.f;

    for (int t = 0; t < NT; t++) {
        if (warp == 0) {
            if (lane == 0) spin_ge(&g_flag[b], t + 1);        // V ready
            if (lane == 1) spin_ge(&g_flag[32 + b], t + 1);   // zA ready
            __syncwarp();
            unsigned m1 = (lane < 16) ? __ldcg(&spkV[(size_t)t * 16 + lane])
                                      : __ldcg(&zAin[(size_t)t * 16 + (lane - 16)]);
            int t1 = build_list(m1, 0, ss->listAtt, 0);
            unsigned m2 = (lane < 16) ? ss->maskR[lane] : 0u;
            int t2 = build_list(m2, 1024, ss->listAtt, t1);
            int tot = t1 + t2;
            if (lane < 16) ss->listAtt[tot + lane] = 0;
            if (lane == 0) ss->totAtt = tot;
        }
        __syncthreads();                                   // B1
        const int nsp = ss->totAtt;

        float acc = gather16_2(Win, Wrec, ss->listAtt, nsp, u, 0.f);

        float an = RHO * a + z, thr = 1.0f + BETA * an;
        float vn = ALPHA * v + acc - z * thr, vsc = vn - thr;
        float zn = (vsc > 0.f) ? 1.f : 0.f;

        unsigned bal = __ballot_sync(0xffffffffu, zn > 0.f);
        if (lane == 0) ss->maskR[warp] = bal;

        const size_t base = (size_t)b * NT + t;
        __stcs(&out1[base * 512 + u], zn);
        __stcs(&out2[base * 3072 + 5 * 512 + u], zn);
        __stcs(&out3[base * 2048 + 3 * 512 + u], thr);
        __stcs(&out4[base * 3072 + 5 * 512 + u], vsc);

        v = vn; a = an; z = zn;
        __syncthreads();                                   // B2
    }
}

// ---------------------------------------------------------------------------
__global__ void reset_kernel()
{
    int i = threadIdx.x;
    if (i < 64) g_flag[i] = 0;
    if (i < 250) g_chunk[i] = 0;
}

__global__ __launch_bounds__(512, 2) void fused_kernel(
    const float* __restrict__ x,
    const float* __restrict__ Wk_in, const float* __restrict__ Wk_rec,
    const float* __restrict__ Wq_in, const float* __restrict__ Wq_rec,
    const float* __restrict__ Wv_in, const float* __restrict__ Wv_rec,
    const float* __restrict__ Watt_in, const float* __restrict__ Watt_rec,
    const float* __restrict__ Wwta_a, const float* __restrict__ Wwta_b,
    float* __restrict__ d_out)
{
    __shared__ __align__(16) unsigned char smem_raw[
        sizeof(GemmSmem) > sizeof(ScanSmem) ? sizeof(GemmSmem) : sizeof(ScanSmem)];
    const int bid = blockIdx.x;

    if (bid >= 96) {
        gemm_role(bid - 96, x, Wk_in, Wq_in, Wv_in, (GemmSmem*)smem_raw);
        return;
    }
    ScanSmem* ss = (ScanSmem*)smem_raw;
    if (bid < 32) {
        kqv_role(bid, Wk_rec, Wq_rec, Wv_rec, d_out, ss);
    } else if (bid < 64) {
        wta_role(bid - 32, Wwta_a, Wwta_b, d_out, ss);
    } else {
        att_role(bid - 64, Watt_in, Watt_rec, d_out, ss);
    }
}

// ---------------------------------------------------------------------------
extern "C" void kernel_launch(void* const* d_in, const int* in_sizes, int n_in,
                              void* d_out, int out_size)
{
    const float* x        = (const float*)d_in[0];
    const float* Wk_in    = (const float*)d_in[1];
    const float* Wk_rec   = (const float*)d_in[2];
    const float* Wq_in    = (const float*)d_in[3];
    const float* Wq_rec   = (const float*)d_in[4];
    const float* Wv_in    = (const float*)d_in[5];
    const float* Wv_rec   = (const float*)d_in[6];
    const float* Watt_in  = (const float*)d_in[7];
    const float* Watt_rec = (const float*)d_in[8];
    const float* Wwta_a   = (const float*)d_in[9];
    const float* Wwta_b   = (const float*)d_in[10];
    float* out = (float*)d_out;

    (void)in_sizes; (void)n_in; (void)out_size;

    reset_kernel<<<1, 256>>>();
    fused_kernel<<<96 + 3000, 512>>>(x, Wk_in, Wk_rec, Wq_in, Wq_rec,
                                     Wv_in, Wv_rec, Watt_in, Watt_rec,
                                     Wwta_a, Wwta_b, out);
}